// round 2
// baseline (speedup 1.0000x reference)
#include <cuda_runtime.h>
#include <math.h>

// Problem constants
#define NN 16384
#define FF 512
#define BB 4
#define MM (NN * BB)          // 65536 token rows
#define GH 128
#define SE_DIM 64
#define EPS 1e-5f

// ---------------- scratch (device globals; no allocation) ----------------
__device__ float g_T[MM * FF];          // tokens (N,B,F) row-major, r = n*4+b
__device__ float g_scr[MM * FF];        // shared: LN output, then attention output
__device__ float g_qkv[MM * 1536];      // qkv, later reused as FFN/MLP hidden
__device__ float g_t2[MM * FF];         // attention residual stream -> x2
__device__ float g_x1[MM * FF];         // conv expert -> fused
__device__ float g_x3[MM * FF];         // mlp expert
__device__ float g_ctx[NN * 1024];      // [mean | max] gating context
__device__ float g_s[NN * FF];          // SE squeeze
__device__ float g_s1[NN * SE_DIM];
__device__ float g_s2[NN * FF];
__device__ float g_gh[NN * GH];
__device__ float g_alpha[NN * 3];

// ---------------- helpers ----------------
__device__ __forceinline__ float gelu_exact(float x) {
    return x * normcdff(x);   // x * Phi(x), exact (erf-based) GELU
}

// block reduce of (sum, sumsq); shm must hold >= 32 floats
__device__ __forceinline__ void block_reduce2(float& s, float& ss, float* shm) {
    int lane = threadIdx.x & 31, warp = threadIdx.x >> 5;
    int nwarps = (blockDim.x + 31) >> 5;
    #pragma unroll
    for (int o = 16; o; o >>= 1) {
        s  += __shfl_xor_sync(0xffffffffu, s, o);
        ss += __shfl_xor_sync(0xffffffffu, ss, o);
    }
    if (lane == 0) { shm[warp] = s; shm[16 + warp] = ss; }
    __syncthreads();
    if (threadIdx.x < 32) {
        float a = (lane < nwarps) ? shm[lane] : 0.f;
        float b = (lane < nwarps) ? shm[16 + lane] : 0.f;
        #pragma unroll
        for (int o = 16; o; o >>= 1) {
            a += __shfl_xor_sync(0xffffffffu, a, o);
            b += __shfl_xor_sync(0xffffffffu, b, o);
        }
        if (lane == 0) { shm[0] = a; shm[16] = b; }
    }
    __syncthreads();
    s = shm[0]; ss = shm[16];
}

// ---------------- tiled SGEMM: C = act(A @ W^T [+ bias] [+ res]) ----------------
// A: M x K row-major, W: Nc x K row-major, C: M x Nc (or transposed store to (n,o,b))
// ACT: 0 none, 1 gelu, 2 relu, 3 sigmoid
template <int ACT, bool HAS_BIAS, bool HAS_RES, bool OUT_TRANS>
__global__ void __launch_bounds__(256)
gemm_kernel(const float* __restrict__ A, const float* __restrict__ W,
            const float* __restrict__ bias, const float* __restrict__ res,
            float* __restrict__ C, int M, int Nc, int K)
{
    const int BM = 128, BN = 128, BK = 8, TM = 8, TN = 8;
    __shared__ float As[BK][BM];
    __shared__ float Bs[BK][BN];

    int bm = blockIdx.y * BM;
    int bn = blockIdx.x * BN;
    int tid = threadIdx.x;
    int tx = tid & 15;         // 16 threads along N
    int ty = tid >> 4;         // 16 threads along M

    int ld_row = tid >> 1;           // 0..127
    int ld_col = (tid & 1) * 4;      // 0 or 4

    int gr = bm + ld_row;
    int gw = bn + ld_row;
    bool a_ok = gr < M;
    bool w_ok = gw < Nc;
    const float* Aptr = A + (size_t)(a_ok ? gr : 0) * K + ld_col;
    const float* Wptr = W + (size_t)(w_ok ? gw : 0) * K + ld_col;

    float acc[TM][TN];
    #pragma unroll
    for (int i = 0; i < TM; i++)
        #pragma unroll
        for (int j = 0; j < TN; j++) acc[i][j] = 0.f;

    // prefetch first k-tile into registers
    float4 av = a_ok ? *reinterpret_cast<const float4*>(Aptr)
                     : make_float4(0.f, 0.f, 0.f, 0.f);
    float4 wv = w_ok ? *reinterpret_cast<const float4*>(Wptr)
                     : make_float4(0.f, 0.f, 0.f, 0.f);

    for (int k0 = 0; k0 < K; k0 += BK) {
        As[ld_col + 0][ld_row] = av.x;
        As[ld_col + 1][ld_row] = av.y;
        As[ld_col + 2][ld_row] = av.z;
        As[ld_col + 3][ld_row] = av.w;
        Bs[ld_col + 0][ld_row] = wv.x;
        Bs[ld_col + 1][ld_row] = wv.y;
        Bs[ld_col + 2][ld_row] = wv.z;
        Bs[ld_col + 3][ld_row] = wv.w;
        __syncthreads();

        // prefetch next k-tile while computing on this one
        if (k0 + BK < K) {
            av = a_ok ? *reinterpret_cast<const float4*>(Aptr + k0 + BK)
                      : make_float4(0.f, 0.f, 0.f, 0.f);
            wv = w_ok ? *reinterpret_cast<const float4*>(Wptr + k0 + BK)
                      : make_float4(0.f, 0.f, 0.f, 0.f);
        }

        #pragma unroll
        for (int k = 0; k < BK; k++) {
            float4 a0 = *reinterpret_cast<const float4*>(&As[k][ty * TM]);
            float4 a1 = *reinterpret_cast<const float4*>(&As[k][ty * TM + 4]);
            float4 b0 = *reinterpret_cast<const float4*>(&Bs[k][tx * TN]);
            float4 b1 = *reinterpret_cast<const float4*>(&Bs[k][tx * TN + 4]);
            float ra[TM] = {a0.x, a0.y, a0.z, a0.w, a1.x, a1.y, a1.z, a1.w};
            float rb[TN] = {b0.x, b0.y, b0.z, b0.w, b1.x, b1.y, b1.z, b1.w};
            #pragma unroll
            for (int i = 0; i < TM; i++)
                #pragma unroll
                for (int j = 0; j < TN; j++)
                    acc[i][j] += ra[i] * rb[j];
        }
        __syncthreads();
    }

    #pragma unroll
    for (int i = 0; i < TM; i++) {
        int row = bm + ty * TM + i;
        if (row >= M) continue;
        #pragma unroll
        for (int j = 0; j < TN; j++) {
            int col = bn + tx * TN + j;
            if (col >= Nc) continue;
            float v = acc[i][j];
            if (HAS_BIAS) v += bias[col];
            if (HAS_RES)  v += res[(size_t)row * Nc + col];
            if (ACT == 1) v = gelu_exact(v);
            else if (ACT == 2) v = fmaxf(v, 0.f);
            else if (ACT == 3) v = 1.f / (1.f + expf(-v));
            if (OUT_TRANS) {
                int n = row >> 2, b = row & 3;
                C[((size_t)n * FF + col) * BB + b] = v;
            } else {
                C[(size_t)row * Nc + col] = v;
            }
        }
    }
}

template <int ACT, bool HAS_BIAS, bool HAS_RES, bool OUT_TRANS>
static void launch_gemm(const float* A, const float* W, const float* bias,
                        const float* res, float* C, int M, int Nc, int K) {
    dim3 grid((Nc + 127) / 128, (M + 127) / 128);
    gemm_kernel<ACT, HAS_BIAS, HAS_RES, OUT_TRANS><<<grid, 256>>>(A, W, bias, res, C, M, Nc, K);
}

// ---------------- prep: branches -> token layout + gating context ----------------
__global__ void prep_kernel(const float* __restrict__ br,
                            float* __restrict__ T, float* __restrict__ ctx)
{
    int idx = blockIdx.x * blockDim.x + threadIdx.x;   // over N*F
    if (idx >= NN * FF) return;
    int n = idx >> 9, f = idx & 511;
    float4 v = *reinterpret_cast<const float4*>(br + (size_t)idx * 4);
    float mean = 0.25f * (v.x + v.y + v.z + v.w);
    float mx = fmaxf(fmaxf(v.x, v.y), fmaxf(v.z, v.w));
    ctx[(size_t)n * 1024 + f] = mean;
    ctx[(size_t)n * 1024 + 512 + f] = mx;
    size_t base = ((size_t)n * 4) * FF + f;
    T[base]        = v.x;
    T[base + 512]  = v.y;
    T[base + 1024] = v.z;
    T[base + 1536] = v.w;
}

// ---------------- row LayerNorm (512 features, 128 threads/row) ----------------
__global__ void ln_kernel(const float* __restrict__ X, const float* __restrict__ w,
                          const float* __restrict__ b, float* __restrict__ Y)
{
    __shared__ float shm[32];
    int r = blockIdx.x;
    int t = threadIdx.x;   // 128
    const float4* x = reinterpret_cast<const float4*>(X + (size_t)r * FF);
    float4 v = x[t];
    float s = v.x + v.y + v.z + v.w;
    float ss = v.x * v.x + v.y * v.y + v.z * v.z + v.w * v.w;
    block_reduce2(s, ss, shm);
    float mean = s * (1.f / 512.f);
    float var = ss * (1.f / 512.f) - mean * mean;
    float inv = rsqrtf(var + EPS);
    float4 wv = reinterpret_cast<const float4*>(w)[t];
    float4 bv = reinterpret_cast<const float4*>(b)[t];
    float4 o;
    o.x = (v.x - mean) * inv * wv.x + bv.x;
    o.y = (v.y - mean) * inv * wv.y + bv.y;
    o.z = (v.z - mean) * inv * wv.z + bv.z;
    o.w = (v.w - mean) * inv * wv.w + bv.w;
    reinterpret_cast<float4*>(Y + (size_t)r * FF)[t] = o;
}

// ---------------- attention (4 tokens, 4 heads, dh=128); warp per head ----------------
__global__ void attn_kernel(const float* __restrict__ qkv, float* __restrict__ ao)
{
    int n = blockIdx.x;
    int h = threadIdx.x >> 5;     // head = warp
    int lane = threadIdx.x & 31;
    const float scale = 0.08838834764831845f;   // 128^-0.5
    float q[4][4], k[4][4], v[4][4];
    const float* base = qkv + (size_t)n * 4 * 1536;
    #pragma unroll
    for (int i = 0; i < 4; i++) {
        const float* row = base + i * 1536 + h * 128;
        #pragma unroll
        for (int m = 0; m < 4; m++) {
            int d = lane + 32 * m;
            q[i][m] = row[d] * scale;
            k[i][m] = row[512 + d];
            v[i][m] = row[1024 + d];
        }
    }
    float att[4][4];
    #pragma unroll
    for (int i = 0; i < 4; i++)
        #pragma unroll
        for (int j = 0; j < 4; j++) {
            float p = q[i][0] * k[j][0] + q[i][1] * k[j][1]
                    + q[i][2] * k[j][2] + q[i][3] * k[j][3];
            #pragma unroll
            for (int o = 16; o; o >>= 1) p += __shfl_xor_sync(0xffffffffu, p, o);
            att[i][j] = p;
        }
    #pragma unroll
    for (int i = 0; i < 4; i++) {
        float mx = fmaxf(fmaxf(att[i][0], att[i][1]), fmaxf(att[i][2], att[i][3]));
        float e0 = expf(att[i][0] - mx), e1 = expf(att[i][1] - mx);
        float e2 = expf(att[i][2] - mx), e3 = expf(att[i][3] - mx);
        float inv = 1.f / (e0 + e1 + e2 + e3);
        att[i][0] = e0 * inv; att[i][1] = e1 * inv;
        att[i][2] = e2 * inv; att[i][3] = e3 * inv;
    }
    #pragma unroll
    for (int i = 0; i < 4; i++)
        #pragma unroll
        for (int m = 0; m < 4; m++) {
            float o = att[i][0] * v[0][m] + att[i][1] * v[1][m]
                    + att[i][2] * v[2][m] + att[i][3] * v[3][m];
            ao[((size_t)(n * 4 + i)) * FF + h * 128 + lane + 32 * m] = o;
        }
}

// ---------------- depthwise conv (k=3 over B) + SE squeeze ----------------
__global__ void dw_kernel(float* __restrict__ x1, const float* __restrict__ dw,
                          float* __restrict__ s)
{
    int idx = blockIdx.x * blockDim.x + threadIdx.x;   // over N*F
    if (idx >= NN * FF) return;
    int n = idx >> 9, f = idx & 511;
    size_t base = ((size_t)n * 4) * FF + f;
    float a = x1[base], b = x1[base + 512], c = x1[base + 1024], d = x1[base + 1536];
    float w0 = dw[f * 3], w1 = dw[f * 3 + 1], w2 = dw[f * 3 + 2];
    float y0 = w1 * a + w2 * b;
    float y1 = w0 * a + w1 * b + w2 * c;
    float y2 = w0 * b + w1 * c + w2 * d;
    float y3 = w0 * c + w1 * d;
    x1[base] = y0; x1[base + 512] = y1; x1[base + 1024] = y2; x1[base + 1536] = y3;
    s[idx] = 0.25f * (y0 + y1 + y2 + y3);
}

// ---------------- SE scale + GroupNorm(1 group over F*B) + GELU ----------------
__global__ void gn_kernel(float* __restrict__ x1, const float* __restrict__ s2,
                          const float* __restrict__ gnw, const float* __restrict__ gnb)
{
    __shared__ float shm[32];
    int n = blockIdx.x;
    int t = threadIdx.x;   // 256
    float vals[8];
    float s = 0.f, ss = 0.f;
    #pragma unroll
    for (int j = 0; j < 8; j++) {
        int e = t + 256 * j;           // 0..2047
        int b = e >> 9, f = e & 511;
        float v = x1[((size_t)(n * 4 + b)) * FF + f] * s2[(size_t)n * FF + f];
        vals[j] = v; s += v; ss += v * v;
    }
    block_reduce2(s, ss, shm);
    float mean = s * (1.f / 2048.f);
    float var = ss * (1.f / 2048.f) - mean * mean;
    float inv = rsqrtf(var + EPS);
    #pragma unroll
    for (int j = 0; j < 8; j++) {
        int e = t + 256 * j;
        int b = e >> 9, f = e & 511;
        float y = (vals[j] - mean) * inv * gnw[f] + gnb[f];
        x1[((size_t)(n * 4 + b)) * FF + f] = gelu_exact(y);
    }
}

// ---------------- gate second layer + softmax -> alpha ----------------
__global__ void gate2_kernel(const float* __restrict__ gh, const float* __restrict__ w2,
                             const float* __restrict__ b2, float* __restrict__ alpha)
{
    int warp = threadIdx.x >> 5, lane = threadIdx.x & 31;
    int n = blockIdx.x * 8 + warp;
    if (n >= NN) return;
    float gv[4];
    #pragma unroll
    for (int m = 0; m < 4; m++) gv[m] = gh[(size_t)n * GH + lane + 32 * m];
    float lg[3];
    #pragma unroll
    for (int e = 0; e < 3; e++) {
        float p = 0.f;
        #pragma unroll
        for (int m = 0; m < 4; m++) p += gv[m] * w2[e * GH + lane + 32 * m];
        #pragma unroll
        for (int o = 16; o; o >>= 1) p += __shfl_xor_sync(0xffffffffu, p, o);
        lg[e] = p + b2[e];
    }
    if (lane == 0) {
        float mx = fmaxf(lg[0], fmaxf(lg[1], lg[2]));
        float e0 = expf(lg[0] - mx), e1 = expf(lg[1] - mx), e2 = expf(lg[2] - mx);
        float inv = 1.f / (e0 + e1 + e2);
        alpha[n * 3 + 0] = e0 * inv;
        alpha[n * 3 + 1] = e1 * inv;
        alpha[n * 3 + 2] = e2 * inv;
    }
}

// ---------------- fuse experts with alpha (in place into x1) ----------------
__global__ void fuse_kernel(float* __restrict__ x1, const float* __restrict__ x2,
                            const float* __restrict__ x3, const float* __restrict__ alpha)
{
    int idx = blockIdx.x * blockDim.x + threadIdx.x;   // over M*128 float4
    if (idx >= MM * (FF / 4)) return;
    int r = idx >> 7;
    int n = r >> 2;
    float a0 = alpha[n * 3 + 0], a1 = alpha[n * 3 + 1], a2 = alpha[n * 3 + 2];
    float4 u = reinterpret_cast<float4*>(x1)[idx];
    float4 v = reinterpret_cast<const float4*>(x2)[idx];
    float4 w = reinterpret_cast<const float4*>(x3)[idx];
    u.x = a0 * u.x + a1 * v.x + a2 * w.x;
    u.y = a0 * u.y + a1 * v.y + a2 * w.y;
    u.z = a0 * u.z + a1 * v.z + a2 * w.z;
    u.w = a0 * u.w + a1 * v.w + a2 * w.w;
    reinterpret_cast<float4*>(x1)[idx] = u;
}

// ---------------- host launch ----------------
static float* sym(const void* symbol) {
    void* p = nullptr;
    cudaGetSymbolAddress(&p, symbol);
    return reinterpret_cast<float*>(p);
}

extern "C" void kernel_launch(void* const* d_in, const int* in_sizes, int n_in,
                              void* d_out, int out_size)
{
    const float* branches   = (const float*)d_in[0];
    const float* conv_pw_w  = (const float*)d_in[1];
    const float* conv_dw_w  = (const float*)d_in[2];
    const float* gn_w       = (const float*)d_in[3];
    const float* gn_b       = (const float*)d_in[4];
    const float* se_w1      = (const float*)d_in[5];
    const float* se_w2      = (const float*)d_in[6];
    const float* ln_attn_w  = (const float*)d_in[7];
    const float* ln_attn_b  = (const float*)d_in[8];
    const float* in_proj_w  = (const float*)d_in[9];
    const float* in_proj_b  = (const float*)d_in[10];
    const float* attn_out_w = (const float*)d_in[11];
    const float* attn_out_b = (const float*)d_in[12];
    const float* ln_ffn_w   = (const float*)d_in[13];
    const float* ln_ffn_b   = (const float*)d_in[14];
    const float* ffn_w1     = (const float*)d_in[15];
    const float* ffn_b1     = (const float*)d_in[16];
    const float* ffn_w2     = (const float*)d_in[17];
    const float* ffn_b2     = (const float*)d_in[18];
    const float* mlp_ln_w   = (const float*)d_in[19];
    const float* mlp_ln_b   = (const float*)d_in[20];
    const float* mlp_w1     = (const float*)d_in[21];
    const float* mlp_b1     = (const float*)d_in[22];
    const float* mlp_w2     = (const float*)d_in[23];
    const float* mlp_b2     = (const float*)d_in[24];
    const float* gate_w1    = (const float*)d_in[25];
    const float* gate_b1    = (const float*)d_in[26];
    const float* gate_w2    = (const float*)d_in[27];
    const float* gate_b2    = (const float*)d_in[28];
    const float* outp_w     = (const float*)d_in[29];
    float* out = (float*)d_out;

    float* T   = sym(g_T);
    float* scr = sym(g_scr);     // LN output / attention output (time-shared)
    float* qkv = sym(g_qkv);     // also reused as FFN/MLP hidden
    float* t2  = sym(g_t2);
    float* x1  = sym(g_x1);
    float* x3  = sym(g_x3);
    float* ctx = sym(g_ctx);
    float* s   = sym(g_s);
    float* s1  = sym(g_s1);
    float* s2  = sym(g_s2);
    float* gh  = sym(g_gh);
    float* alpha = sym(g_alpha);

    const int EW_BLOCKS = (NN * FF) / 256;   // 32768

    // 0. tokens + gating context
    prep_kernel<<<EW_BLOCKS, 256>>>(branches, T, ctx);

    // gating
    launch_gemm<1, true, false, false>(ctx, gate_w1, gate_b1, nullptr, gh, NN, GH, 1024);
    gate2_kernel<<<NN / 8, 256>>>(gh, gate_w2, gate_b2, alpha);

    // ---- conv expert ----
    launch_gemm<0, false, false, false>(T, conv_pw_w, nullptr, nullptr, x1, MM, FF, FF);
    dw_kernel<<<EW_BLOCKS, 256>>>(x1, conv_dw_w, s);
    launch_gemm<2, false, false, false>(s, se_w1, nullptr, nullptr, s1, NN, SE_DIM, FF);
    launch_gemm<3, false, false, false>(s1, se_w2, nullptr, nullptr, s2, NN, FF, SE_DIM);
    gn_kernel<<<NN, 256>>>(x1, s2, gn_w, gn_b);

    // ---- attention expert ----
    ln_kernel<<<MM, 128>>>(T, ln_attn_w, ln_attn_b, scr);
    launch_gemm<0, true, false, false>(scr, in_proj_w, in_proj_b, nullptr, qkv, MM, 1536, FF);
    attn_kernel<<<NN, 128>>>(qkv, scr);
    launch_gemm<0, true, true, false>(scr, attn_out_w, attn_out_b, T, t2, MM, FF, FF);
    ln_kernel<<<MM, 128>>>(t2, ln_ffn_w, ln_ffn_b, scr);
    launch_gemm<1, true, false, false>(scr, ffn_w1, ffn_b1, nullptr, qkv, MM, 1024, FF);
    launch_gemm<0, true, true, false>(qkv, ffn_w2, ffn_b2, t2, t2, MM, FF, 1024);
    // t2 now holds x2

    // ---- MLP expert ----
    ln_kernel<<<MM, 128>>>(T, mlp_ln_w, mlp_ln_b, scr);
    launch_gemm<1, true, false, false>(scr, mlp_w1, mlp_b1, nullptr, qkv, MM, 1024, FF);
    launch_gemm<0, true, true, false>(qkv, mlp_w2, mlp_b2, T, x3, MM, FF, 1024);

    // ---- fuse + output projection (transposed store to (n,o,b)) ----
    fuse_kernel<<<(MM * (FF / 4)) / 256, 256>>>(x1, t2, x3, alpha);
    launch_gemm<0, false, false, true>(x1, outp_w, nullptr, nullptr, out, MM, FF, FF);
}

// round 5
// speedup vs baseline: 1.1357x; 1.1357x over previous
#include <cuda_runtime.h>
#include <math.h>
#include <stdint.h>

// Problem constants
#define NN 16384
#define FF 512
#define BB 4
#define MM (NN * BB)          // 65536 token rows
#define GH 128
#define SE_DIM 64
#define EPS 1e-5f

// ---------------- scratch (device globals; no allocation) ----------------
__device__ float g_T[MM * FF];          // tokens (N,B,F) row-major, r = n*4+b
__device__ float g_scr[MM * FF];        // shared: LN output, then attention output
__device__ float g_qkv[MM * 1536];      // qkv, later reused as FFN/MLP hidden
__device__ float g_t2[MM * FF];         // attention residual stream -> x2
__device__ float g_x1[MM * FF];         // conv expert -> fused
__device__ float g_x3[MM * FF];         // mlp expert
__device__ float g_ctx[NN * 1024];      // [mean | max] gating context
__device__ float g_s[NN * FF];          // SE squeeze
__device__ float g_s1[NN * SE_DIM];
__device__ float g_s2[NN * FF];
__device__ float g_gh[NN * GH];
__device__ float g_alpha[NN * 3];

// ---------------- helpers ----------------
__device__ __forceinline__ float gelu_exact(float x) {
    return x * normcdff(x);
}

__device__ __forceinline__ uint32_t cvt_tf32(float x) {
    uint32_t u;
    asm("cvt.rna.tf32.f32 %0, %1;" : "=r"(u) : "f"(x));
    return u;
}

__device__ __forceinline__ void mma_tf32(float* c, const uint32_t* a, const uint32_t* b) {
    asm volatile(
        "mma.sync.aligned.m16n8k8.row.col.f32.tf32.tf32.f32 "
        "{%0,%1,%2,%3}, {%4,%5,%6,%7}, {%8,%9}, {%0,%1,%2,%3};\n"
        : "+f"(c[0]), "+f"(c[1]), "+f"(c[2]), "+f"(c[3])
        : "r"(a[0]), "r"(a[1]), "r"(a[2]), "r"(a[3]), "r"(b[0]), "r"(b[1]));
}

// block reduce of (sum, sumsq); shm must hold >= 32 floats
__device__ __forceinline__ void block_reduce2(float& s, float& ss, float* shm) {
    int lane = threadIdx.x & 31, warp = threadIdx.x >> 5;
    int nwarps = (blockDim.x + 31) >> 5;
    #pragma unroll
    for (int o = 16; o; o >>= 1) {
        s  += __shfl_xor_sync(0xffffffffu, s, o);
        ss += __shfl_xor_sync(0xffffffffu, ss, o);
    }
    if (lane == 0) { shm[warp] = s; shm[16 + warp] = ss; }
    __syncthreads();
    if (threadIdx.x < 32) {
        float a = (lane < nwarps) ? shm[lane] : 0.f;
        float b = (lane < nwarps) ? shm[16 + lane] : 0.f;
        #pragma unroll
        for (int o = 16; o; o >>= 1) {
            a += __shfl_xor_sync(0xffffffffu, a, o);
            b += __shfl_xor_sync(0xffffffffu, b, o);
        }
        if (lane == 0) { shm[0] = a; shm[16] = b; }
    }
    __syncthreads();
    s = shm[0]; ss = shm[16];
}

// =====================================================================
// Tensor-core SGEMM (3xTF32): C = act(A @ W^T [+ bias] [+ res])
// Requires M % 128 == 0, Nc % 128 == 0, K % 16 == 0.
// A: M x K row-major, W: Nc x K row-major.
// ACT: 0 none, 1 gelu, 2 relu, 3 sigmoid
// =====================================================================
template <int ACT, bool HAS_BIAS, bool HAS_RES, bool OUT_TRANS>
__global__ void __launch_bounds__(256)
gemm_tc_kernel(const float* __restrict__ A, const float* __restrict__ W,
               const float* __restrict__ bias, const float* __restrict__ res,
               float* __restrict__ C, int M, int Nc, int K)
{
    const int BM = 128, BN = 128, BK = 16, SA = 132;   // SA: smem row stride (floats)
    __shared__ uint32_t Ah[BK * SA];
    __shared__ uint32_t Al[BK * SA];
    __shared__ uint32_t Bh[BK * SA];
    __shared__ uint32_t Bl[BK * SA];

    int tid = threadIdx.x;
    int wid = tid >> 5, lane = tid & 31;
    int wm = (wid >> 2) * 64;    // warp row offset within block (0 or 64)
    int wn = (wid & 3) * 32;     // warp col offset within block
    int bm = blockIdx.y * BM;
    int bn = blockIdx.x * BN;

    // global loads: thread -> row tid/2, 8 consecutive k at (tid&1)*8
    int lrow = tid >> 1;
    int lcol = (tid & 1) * 8;
    const float* Aptr = A + (size_t)(bm + lrow) * K + lcol;
    const float* Wptr = W + (size_t)(bn + lrow) * K + lcol;

    float acc[4][4][4];
    #pragma unroll
    for (int i = 0; i < 4; i++)
        #pragma unroll
        for (int j = 0; j < 4; j++)
            #pragma unroll
            for (int r = 0; r < 4; r++) acc[i][j][r] = 0.f;

    // prefetch first k-tile
    float4 av0 = *reinterpret_cast<const float4*>(Aptr);
    float4 av1 = *reinterpret_cast<const float4*>(Aptr + 4);
    float4 wv0 = *reinterpret_cast<const float4*>(Wptr);
    float4 wv1 = *reinterpret_cast<const float4*>(Wptr + 4);

    int klane = lane & 3;        // k offset within fragment
    int glane = lane >> 2;       // group id

    for (int k0 = 0; k0 < K; k0 += BK) {
        // split-convert and stage into smem (layout [k][m])
        {
            float va[8] = {av0.x, av0.y, av0.z, av0.w, av1.x, av1.y, av1.z, av1.w};
            float vw[8] = {wv0.x, wv0.y, wv0.z, wv0.w, wv1.x, wv1.y, wv1.z, wv1.w};
            #pragma unroll
            for (int j = 0; j < 8; j++) {
                int kk = lcol + j;
                uint32_t hi = cvt_tf32(va[j]);
                Ah[kk * SA + lrow] = hi;
                Al[kk * SA + lrow] = cvt_tf32(va[j] - __uint_as_float(hi));
                uint32_t whi = cvt_tf32(vw[j]);
                Bh[kk * SA + lrow] = whi;
                Bl[kk * SA + lrow] = cvt_tf32(vw[j] - __uint_as_float(whi));
            }
        }
        __syncthreads();

        // prefetch next tile
        if (k0 + BK < K) {
            av0 = *reinterpret_cast<const float4*>(Aptr + k0 + BK);
            av1 = *reinterpret_cast<const float4*>(Aptr + k0 + BK + 4);
            wv0 = *reinterpret_cast<const float4*>(Wptr + k0 + BK);
            wv1 = *reinterpret_cast<const float4*>(Wptr + k0 + BK + 4);
        }

        #pragma unroll
        for (int ks = 0; ks < BK; ks += 8) {
            uint32_t ah[4][4], al[4][4], bh[4][2], bl[4][2];
            int kr0 = (ks + klane) * SA;
            int kr4 = (ks + klane + 4) * SA;
            #pragma unroll
            for (int ti = 0; ti < 4; ti++) {
                int m = wm + ti * 16 + glane;
                ah[ti][0] = Ah[kr0 + m];
                ah[ti][1] = Ah[kr0 + m + 8];
                ah[ti][2] = Ah[kr4 + m];
                ah[ti][3] = Ah[kr4 + m + 8];
                al[ti][0] = Al[kr0 + m];
                al[ti][1] = Al[kr0 + m + 8];
                al[ti][2] = Al[kr4 + m];
                al[ti][3] = Al[kr4 + m + 8];
            }
            #pragma unroll
            for (int tj = 0; tj < 4; tj++) {
                int n = wn + tj * 8 + glane;
                bh[tj][0] = Bh[kr0 + n];
                bh[tj][1] = Bh[kr4 + n];
                bl[tj][0] = Bl[kr0 + n];
                bl[tj][1] = Bl[kr4 + n];
            }
            #pragma unroll
            for (int ti = 0; ti < 4; ti++)
                #pragma unroll
                for (int tj = 0; tj < 4; tj++) {
                    mma_tf32(acc[ti][tj], ah[ti], bh[tj]);
                    mma_tf32(acc[ti][tj], al[ti], bh[tj]);
                    mma_tf32(acc[ti][tj], ah[ti], bl[tj]);
                }
        }
        __syncthreads();
    }

    // epilogue: c0:(r0,c0) c1:(r0,c0+1) c2:(r0+8,c0) c3:(r0+8,c0+1)
    #pragma unroll
    for (int ti = 0; ti < 4; ti++) {
        int row0 = bm + wm + ti * 16 + glane;
        #pragma unroll
        for (int tj = 0; tj < 4; tj++) {
            int col = bn + wn + tj * 8 + 2 * klane;
            #pragma unroll
            for (int half = 0; half < 2; half++) {
                int row = row0 + half * 8;
                float v0 = acc[ti][tj][half * 2 + 0];
                float v1 = acc[ti][tj][half * 2 + 1];
                if (HAS_BIAS) { v0 += bias[col]; v1 += bias[col + 1]; }
                if (HAS_RES) {
                    float2 rv = *reinterpret_cast<const float2*>(res + (size_t)row * Nc + col);
                    v0 += rv.x; v1 += rv.y;
                }
                if (ACT == 1) { v0 = gelu_exact(v0); v1 = gelu_exact(v1); }
                else if (ACT == 2) { v0 = fmaxf(v0, 0.f); v1 = fmaxf(v1, 0.f); }
                else if (ACT == 3) {
                    v0 = 1.f / (1.f + expf(-v0));
                    v1 = 1.f / (1.f + expf(-v1));
                }
                if (OUT_TRANS) {
                    int n = row >> 2, b = row & 3;
                    C[((size_t)n * FF + col) * BB + b] = v0;
                    C[((size_t)n * FF + col + 1) * BB + b] = v1;
                } else {
                    float2 ov = make_float2(v0, v1);
                    *reinterpret_cast<float2*>(C + (size_t)row * Nc + col) = ov;
                }
            }
        }
    }
}

template <int ACT, bool HAS_BIAS, bool HAS_RES, bool OUT_TRANS>
static void launch_tc(const float* A, const float* W, const float* bias,
                      const float* res, float* C, int M, int Nc, int K) {
    dim3 grid(Nc / 128, M / 128);
    gemm_tc_kernel<ACT, HAS_BIAS, HAS_RES, OUT_TRANS><<<grid, 256>>>(A, W, bias, res, C, M, Nc, K);
}

// ---------------- fp32 fallback GEMM (small/odd shapes: SE1) ----------------
template <int ACT>
__global__ void __launch_bounds__(256)
gemm_kernel(const float* __restrict__ A, const float* __restrict__ W,
            float* __restrict__ C, int M, int Nc, int K)
{
    const int BM = 128, BN = 128, BK = 8, TM = 8, TN = 8;
    __shared__ float As[BK][BM];
    __shared__ float Bs[BK][BN];

    int bm = blockIdx.y * BM;
    int bn = blockIdx.x * BN;
    int tid = threadIdx.x;
    int tx = tid & 15;
    int ty = tid >> 4;

    int ld_row = tid >> 1;
    int ld_col = (tid & 1) * 4;

    int gr = bm + ld_row;
    int gw = bn + ld_row;
    bool a_ok = gr < M;
    bool w_ok = gw < Nc;
    const float* Aptr = A + (size_t)(a_ok ? gr : 0) * K + ld_col;
    const float* Wptr = W + (size_t)(w_ok ? gw : 0) * K + ld_col;

    float acc[TM][TN];
    #pragma unroll
    for (int i = 0; i < TM; i++)
        #pragma unroll
        for (int j = 0; j < TN; j++) acc[i][j] = 0.f;

    float4 av = a_ok ? *reinterpret_cast<const float4*>(Aptr)
                     : make_float4(0.f, 0.f, 0.f, 0.f);
    float4 wv = w_ok ? *reinterpret_cast<const float4*>(Wptr)
                     : make_float4(0.f, 0.f, 0.f, 0.f);

    for (int k0 = 0; k0 < K; k0 += BK) {
        As[ld_col + 0][ld_row] = av.x;
        As[ld_col + 1][ld_row] = av.y;
        As[ld_col + 2][ld_row] = av.z;
        As[ld_col + 3][ld_row] = av.w;
        Bs[ld_col + 0][ld_row] = wv.x;
        Bs[ld_col + 1][ld_row] = wv.y;
        Bs[ld_col + 2][ld_row] = wv.z;
        Bs[ld_col + 3][ld_row] = wv.w;
        __syncthreads();

        if (k0 + BK < K) {
            av = a_ok ? *reinterpret_cast<const float4*>(Aptr + k0 + BK)
                      : make_float4(0.f, 0.f, 0.f, 0.f);
            wv = w_ok ? *reinterpret_cast<const float4*>(Wptr + k0 + BK)
                      : make_float4(0.f, 0.f, 0.f, 0.f);
        }

        #pragma unroll
        for (int k = 0; k < BK; k++) {
            float4 a0 = *reinterpret_cast<const float4*>(&As[k][ty * TM]);
            float4 a1 = *reinterpret_cast<const float4*>(&As[k][ty * TM + 4]);
            float4 b0 = *reinterpret_cast<const float4*>(&Bs[k][tx * TN]);
            float4 b1 = *reinterpret_cast<const float4*>(&Bs[k][tx * TN + 4]);
            float ra[TM] = {a0.x, a0.y, a0.z, a0.w, a1.x, a1.y, a1.z, a1.w};
            float rb[TN] = {b0.x, b0.y, b0.z, b0.w, b1.x, b1.y, b1.z, b1.w};
            #pragma unroll
            for (int i = 0; i < TM; i++)
                #pragma unroll
                for (int j = 0; j < TN; j++)
                    acc[i][j] += ra[i] * rb[j];
        }
        __syncthreads();
    }

    #pragma unroll
    for (int i = 0; i < TM; i++) {
        int row = bm + ty * TM + i;
        if (row >= M) continue;
        #pragma unroll
        for (int j = 0; j < TN; j++) {
            int col = bn + tx * TN + j;
            if (col >= Nc) continue;
            float v = acc[i][j];
            if (ACT == 2) v = fmaxf(v, 0.f);
            C[(size_t)row * Nc + col] = v;
        }
    }
}

// ---------------- prep: branches -> token layout + gating context ----------------
__global__ void prep_kernel(const float* __restrict__ br,
                            float* __restrict__ T, float* __restrict__ ctx)
{
    int idx = blockIdx.x * blockDim.x + threadIdx.x;   // over N*F
    if (idx >= NN * FF) return;
    int n = idx >> 9, f = idx & 511;
    float4 v = *reinterpret_cast<const float4*>(br + (size_t)idx * 4);
    float mean = 0.25f * (v.x + v.y + v.z + v.w);
    float mx = fmaxf(fmaxf(v.x, v.y), fmaxf(v.z, v.w));
    ctx[(size_t)n * 1024 + f] = mean;
    ctx[(size_t)n * 1024 + 512 + f] = mx;
    size_t base = ((size_t)n * 4) * FF + f;
    T[base]        = v.x;
    T[base + 512]  = v.y;
    T[base + 1024] = v.z;
    T[base + 1536] = v.w;
}

// ---------------- row LayerNorm (512 features, 128 threads/row) ----------------
__global__ void ln_kernel(const float* __restrict__ X, const float* __restrict__ w,
                          const float* __restrict__ b, float* __restrict__ Y)
{
    __shared__ float shm[32];
    int r = blockIdx.x;
    int t = threadIdx.x;   // 128
    const float4* x = reinterpret_cast<const float4*>(X + (size_t)r * FF);
    float4 v = x[t];
    float s = v.x + v.y + v.z + v.w;
    float ss = v.x * v.x + v.y * v.y + v.z * v.z + v.w * v.w;
    block_reduce2(s, ss, shm);
    float mean = s * (1.f / 512.f);
    float var = ss * (1.f / 512.f) - mean * mean;
    float inv = rsqrtf(var + EPS);
    float4 wv = reinterpret_cast<const float4*>(w)[t];
    float4 bv = reinterpret_cast<const float4*>(b)[t];
    float4 o;
    o.x = (v.x - mean) * inv * wv.x + bv.x;
    o.y = (v.y - mean) * inv * wv.y + bv.y;
    o.z = (v.z - mean) * inv * wv.z + bv.z;
    o.w = (v.w - mean) * inv * wv.w + bv.w;
    reinterpret_cast<float4*>(Y + (size_t)r * FF)[t] = o;
}

// ---------------- attention (4 tokens, 4 heads, dh=128); warp per head ----------------
__global__ void attn_kernel(const float* __restrict__ qkv, float* __restrict__ ao)
{
    int n = blockIdx.x;
    int h = threadIdx.x >> 5;
    int lane = threadIdx.x & 31;
    const float scale = 0.08838834764831845f;   // 128^-0.5
    float q[4][4], k[4][4], v[4][4];
    const float* base = qkv + (size_t)n * 4 * 1536;
    #pragma unroll
    for (int i = 0; i < 4; i++) {
        const float* row = base + i * 1536 + h * 128;
        #pragma unroll
        for (int m = 0; m < 4; m++) {
            int d = lane + 32 * m;
            q[i][m] = row[d] * scale;
            k[i][m] = row[512 + d];
            v[i][m] = row[1024 + d];
        }
    }
    float att[4][4];
    #pragma unroll
    for (int i = 0; i < 4; i++)
        #pragma unroll
        for (int j = 0; j < 4; j++) {
            float p = q[i][0] * k[j][0] + q[i][1] * k[j][1]
                    + q[i][2] * k[j][2] + q[i][3] * k[j][3];
            #pragma unroll
            for (int o = 16; o; o >>= 1) p += __shfl_xor_sync(0xffffffffu, p, o);
            att[i][j] = p;
        }
    #pragma unroll
    for (int i = 0; i < 4; i++) {
        float mx = fmaxf(fmaxf(att[i][0], att[i][1]), fmaxf(att[i][2], att[i][3]));
        float e0 = expf(att[i][0] - mx), e1 = expf(att[i][1] - mx);
        float e2 = expf(att[i][2] - mx), e3 = expf(att[i][3] - mx);
        float inv = 1.f / (e0 + e1 + e2 + e3);
        att[i][0] = e0 * inv; att[i][1] = e1 * inv;
        att[i][2] = e2 * inv; att[i][3] = e3 * inv;
    }
    #pragma unroll
    for (int i = 0; i < 4; i++)
        #pragma unroll
        for (int m = 0; m < 4; m++) {
            float o = att[i][0] * v[0][m] + att[i][1] * v[1][m]
                    + att[i][2] * v[2][m] + att[i][3] * v[3][m];
            ao[((size_t)(n * 4 + i)) * FF + h * 128 + lane + 32 * m] = o;
        }
}

// ---------------- depthwise conv (k=3 over B) + SE squeeze ----------------
__global__ void dw_kernel(float* __restrict__ x1, const float* __restrict__ dw,
                          float* __restrict__ s)
{
    int idx = blockIdx.x * blockDim.x + threadIdx.x;   // over N*F
    if (idx >= NN * FF) return;
    int n = idx >> 9, f = idx & 511;
    size_t base = ((size_t)n * 4) * FF + f;
    float a = x1[base], b = x1[base + 512], c = x1[base + 1024], d = x1[base + 1536];
    float w0 = dw[f * 3], w1 = dw[f * 3 + 1], w2 = dw[f * 3 + 2];
    float y0 = w1 * a + w2 * b;
    float y1 = w0 * a + w1 * b + w2 * c;
    float y2 = w0 * b + w1 * c + w2 * d;
    float y3 = w0 * c + w1 * d;
    x1[base] = y0; x1[base + 512] = y1; x1[base + 1024] = y2; x1[base + 1536] = y3;
    s[idx] = 0.25f * (y0 + y1 + y2 + y3);
}

// ---------------- SE scale + GroupNorm(1 group over F*B) + GELU ----------------
__global__ void gn_kernel(float* __restrict__ x1, const float* __restrict__ s2,
                          const float* __restrict__ gnw, const float* __restrict__ gnb)
{
    __shared__ float shm[32];
    int n = blockIdx.x;
    int t = threadIdx.x;   // 256
    float vals[8];
    float s = 0.f, ss = 0.f;
    #pragma unroll
    for (int j = 0; j < 8; j++) {
        int e = t + 256 * j;
        int b = e >> 9, f = e & 511;
        float v = x1[((size_t)(n * 4 + b)) * FF + f] * s2[(size_t)n * FF + f];
        vals[j] = v; s += v; ss += v * v;
    }
    block_reduce2(s, ss, shm);
    float mean = s * (1.f / 2048.f);
    float var = ss * (1.f / 2048.f) - mean * mean;
    float inv = rsqrtf(var + EPS);
    #pragma unroll
    for (int j = 0; j < 8; j++) {
        int e = t + 256 * j;
        int b = e >> 9, f = e & 511;
        float y = (vals[j] - mean) * inv * gnw[f] + gnb[f];
        x1[((size_t)(n * 4 + b)) * FF + f] = gelu_exact(y);
    }
}

// ---------------- gate second layer + softmax -> alpha ----------------
__global__ void gate2_kernel(const float* __restrict__ gh, const float* __restrict__ w2,
                             const float* __restrict__ b2, float* __restrict__ alpha)
{
    int warp = threadIdx.x >> 5, lane = threadIdx.x & 31;
    int n = blockIdx.x * 8 + warp;
    if (n >= NN) return;
    float gv[4];
    #pragma unroll
    for (int m = 0; m < 4; m++) gv[m] = gh[(size_t)n * GH + lane + 32 * m];
    float lg[3];
    #pragma unroll
    for (int e = 0; e < 3; e++) {
        float p = 0.f;
        #pragma unroll
        for (int m = 0; m < 4; m++) p += gv[m] * w2[e * GH + lane + 32 * m];
        #pragma unroll
        for (int o = 16; o; o >>= 1) p += __shfl_xor_sync(0xffffffffu, p, o);
        lg[e] = p + b2[e];
    }
    if (lane == 0) {
        float mx = fmaxf(lg[0], fmaxf(lg[1], lg[2]));
        float e0 = expf(lg[0] - mx), e1 = expf(lg[1] - mx), e2 = expf(lg[2] - mx);
        float inv = 1.f / (e0 + e1 + e2);
        alpha[n * 3 + 0] = e0 * inv;
        alpha[n * 3 + 1] = e1 * inv;
        alpha[n * 3 + 2] = e2 * inv;
    }
}

// ---------------- fuse experts with alpha (in place into x1) ----------------
__global__ void fuse_kernel(float* __restrict__ x1, const float* __restrict__ x2,
                            const float* __restrict__ x3, const float* __restrict__ alpha)
{
    int idx = blockIdx.x * blockDim.x + threadIdx.x;   // over M*128 float4
    if (idx >= MM * (FF / 4)) return;
    int r = idx >> 7;
    int n = r >> 2;
    float a0 = alpha[n * 3 + 0], a1 = alpha[n * 3 + 1], a2 = alpha[n * 3 + 2];
    float4 u = reinterpret_cast<float4*>(x1)[idx];
    float4 v = reinterpret_cast<const float4*>(x2)[idx];
    float4 w = reinterpret_cast<const float4*>(x3)[idx];
    u.x = a0 * u.x + a1 * v.x + a2 * w.x;
    u.y = a0 * u.y + a1 * v.y + a2 * w.y;
    u.z = a0 * u.z + a1 * v.z + a2 * w.z;
    u.w = a0 * u.w + a1 * v.w + a2 * w.w;
    reinterpret_cast<float4*>(x1)[idx] = u;
}

// ---------------- host launch ----------------
static float* sym(const void* symbol) {
    void* p = nullptr;
    cudaGetSymbolAddress(&p, symbol);
    return reinterpret_cast<float*>(p);
}

extern "C" void kernel_launch(void* const* d_in, const int* in_sizes, int n_in,
                              void* d_out, int out_size)
{
    const float* branches   = (const float*)d_in[0];
    const float* conv_pw_w  = (const float*)d_in[1];
    const float* conv_dw_w  = (const float*)d_in[2];
    const float* gn_w       = (const float*)d_in[3];
    const float* gn_b       = (const float*)d_in[4];
    const float* se_w1      = (const float*)d_in[5];
    const float* se_w2      = (const float*)d_in[6];
    const float* ln_attn_w  = (const float*)d_in[7];
    const float* ln_attn_b  = (const float*)d_in[8];
    const float* in_proj_w  = (const float*)d_in[9];
    const float* in_proj_b  = (const float*)d_in[10];
    const float* attn_out_w = (const float*)d_in[11];
    const float* attn_out_b = (const float*)d_in[12];
    const float* ln_ffn_w   = (const float*)d_in[13];
    const float* ln_ffn_b   = (const float*)d_in[14];
    const float* ffn_w1     = (const float*)d_in[15];
    const float* ffn_b1     = (const float*)d_in[16];
    const float* ffn_w2     = (const float*)d_in[17];
    const float* ffn_b2     = (const float*)d_in[18];
    const float* mlp_ln_w   = (const float*)d_in[19];
    const float* mlp_ln_b   = (const float*)d_in[20];
    const float* mlp_w1     = (const float*)d_in[21];
    const float* mlp_b1     = (const float*)d_in[22];
    const float* mlp_w2     = (const float*)d_in[23];
    const float* mlp_b2     = (const float*)d_in[24];
    const float* gate_w1    = (const float*)d_in[25];
    const float* gate_b1    = (const float*)d_in[26];
    const float* gate_w2    = (const float*)d_in[27];
    const float* gate_b2    = (const float*)d_in[28];
    const float* outp_w     = (const float*)d_in[29];
    float* out = (float*)d_out;

    float* T   = sym(g_T);
    float* scr = sym(g_scr);
    float* qkv = sym(g_qkv);
    float* t2  = sym(g_t2);
    float* x1  = sym(g_x1);
    float* x3  = sym(g_x3);
    float* ctx = sym(g_ctx);
    float* s   = sym(g_s);
    float* s1  = sym(g_s1);
    float* s2  = sym(g_s2);
    float* gh  = sym(g_gh);
    float* alpha = sym(g_alpha);

    const int EW_BLOCKS = (NN * FF) / 256;   // 32768

    // 0. tokens + gating context
    prep_kernel<<<EW_BLOCKS, 256>>>(branches, T, ctx);

    // gating
    launch_tc<1, true, false, false>(ctx, gate_w1, gate_b1, nullptr, gh, NN, GH, 1024);
    gate2_kernel<<<NN / 8, 256>>>(gh, gate_w2, gate_b2, alpha);

    // ---- conv expert ----
    launch_tc<0, false, false, false>(T, conv_pw_w, nullptr, nullptr, x1, MM, FF, FF);
    dw_kernel<<<EW_BLOCKS, 256>>>(x1, conv_dw_w, s);
    {   // SE1: Nc=64 -> fp32 fallback
        dim3 grid((SE_DIM + 127) / 128, (NN + 127) / 128);
        gemm_kernel<2><<<grid, 256>>>(s, se_w1, s1, NN, SE_DIM, FF);
    }
    launch_tc<3, false, false, false>(s1, se_w2, nullptr, nullptr, s2, NN, FF, SE_DIM);
    gn_kernel<<<NN, 256>>>(x1, s2, gn_w, gn_b);

    // ---- attention expert ----
    ln_kernel<<<MM, 128>>>(T, ln_attn_w, ln_attn_b, scr);
    launch_tc<0, true, false, false>(scr, in_proj_w, in_proj_b, nullptr, qkv, MM, 1536, FF);
    attn_kernel<<<NN, 128>>>(qkv, scr);
    launch_tc<0, true, true, false>(scr, attn_out_w, attn_out_b, T, t2, MM, FF, FF);
    ln_kernel<<<MM, 128>>>(t2, ln_ffn_w, ln_ffn_b, scr);
    launch_tc<1, true, false, false>(scr, ffn_w1, ffn_b1, nullptr, qkv, MM, 1024, FF);
    launch_tc<0, true, true, false>(qkv, ffn_w2, ffn_b2, t2, t2, MM, FF, 1024);
    // t2 now holds x2

    // ---- MLP expert ----
    ln_kernel<<<MM, 128>>>(T, mlp_ln_w, mlp_ln_b, scr);
    launch_tc<1, true, false, false>(scr, mlp_w1, mlp_b1, nullptr, qkv, MM, 1024, FF);
    launch_tc<0, true, true, false>(qkv, mlp_w2, mlp_b2, T, x3, MM, FF, 1024);

    // ---- fuse + output projection (transposed store to (n,o,b)) ----
    fuse_kernel<<<(MM * (FF / 4)) / 256, 256>>>(x1, t2, x3, alpha);
    launch_tc<0, false, false, true>(x1, outp_w, nullptr, nullptr, out, MM, FF, FF);
}

// round 7
// speedup vs baseline: 1.2438x; 1.0952x over previous
#include <cuda_runtime.h>
#include <math.h>
#include <stdint.h>

// Problem constants
#define NN 16384
#define FF 512
#define BB 4
#define MM (NN * BB)          // 65536 token rows
#define GH 128
#define SE_DIM 64
#define EPS 1e-5f

// ---------------- scratch (device globals; no allocation) ----------------
__device__ float g_T[MM * FF];          // tokens (N,B,F) row-major, r = n*4+b
__device__ float g_scr[MM * FF];        // shared: LN output, then attention output
__device__ float g_qkv[MM * 1536];      // qkv, later reused as FFN/MLP hidden
__device__ float g_t2[MM * FF];         // attention residual stream -> x2
__device__ float g_x1[MM * FF];         // conv expert -> fused
__device__ float g_x3[MM * FF];         // mlp expert
__device__ float g_ctx[NN * 1024];      // [mean | max] gating context
__device__ float g_s[NN * FF];          // SE squeeze
__device__ float g_s1[NN * SE_DIM];
__device__ float g_s2[NN * FF];
__device__ float g_gh[NN * GH];
__device__ float g_alpha[NN * 3];

// ---------------- helpers ----------------
__device__ __forceinline__ float gelu_exact(float x) {
    return x * normcdff(x);
}

__device__ __forceinline__ uint32_t cvt_tf32(float x) {
    uint32_t u;
    asm("cvt.rna.tf32.f32 %0, %1;" : "=r"(u) : "f"(x));
    return u;
}

__device__ __forceinline__ void mma_tf32(float* c, const uint32_t* a, const uint32_t* b) {
    asm volatile(
        "mma.sync.aligned.m16n8k8.row.col.f32.tf32.tf32.f32 "
        "{%0,%1,%2,%3}, {%4,%5,%6,%7}, {%8,%9}, {%0,%1,%2,%3};\n"
        : "+f"(c[0]), "+f"(c[1]), "+f"(c[2]), "+f"(c[3])
        : "r"(a[0]), "r"(a[1]), "r"(a[2]), "r"(a[3]), "r"(b[0]), "r"(b[1]));
}

// block reduce of (sum, sumsq); shm must hold >= 32 floats
__device__ __forceinline__ void block_reduce2(float& s, float& ss, float* shm) {
    int lane = threadIdx.x & 31, warp = threadIdx.x >> 5;
    int nwarps = (blockDim.x + 31) >> 5;
    #pragma unroll
    for (int o = 16; o; o >>= 1) {
        s  += __shfl_xor_sync(0xffffffffu, s, o);
        ss += __shfl_xor_sync(0xffffffffu, ss, o);
    }
    if (lane == 0) { shm[warp] = s; shm[16 + warp] = ss; }
    __syncthreads();
    if (threadIdx.x < 32) {
        float a = (lane < nwarps) ? shm[lane] : 0.f;
        float b = (lane < nwarps) ? shm[16 + lane] : 0.f;
        #pragma unroll
        for (int o = 16; o; o >>= 1) {
            a += __shfl_xor_sync(0xffffffffu, a, o);
            b += __shfl_xor_sync(0xffffffffu, b, o);
        }
        if (lane == 0) { shm[0] = a; shm[16] = b; }
    }
    __syncthreads();
    s = shm[0]; ss = shm[16];
}

// =====================================================================
// Tensor-core SGEMM (3xTF32): C = act(A @ W^T [+ bias] [+ res])
// Requires M % 128 == 0, Nc % 128 == 0, K % 8 == 0.
// A: M x K row-major, W: Nc x K row-major.
// hi/lo interleaved as uint2 -> LDS.64 fragment loads, conflict-free
// banks ([k][m], k-stride 132 uint2 = 8 banks), ping-pong double buffer.
// ACT: 0 none, 1 gelu, 2 relu, 3 sigmoid
// =====================================================================
template <int ACT, bool HAS_BIAS, bool HAS_RES, bool OUT_TRANS>
__global__ void __launch_bounds__(256)
gemm_tc_kernel(const float* __restrict__ A, const float* __restrict__ W,
               const float* __restrict__ bias, const float* __restrict__ res,
               float* __restrict__ C, int M, int Nc, int K)
{
    const int BK = 8, SA = 132;   // SA: smem k-row stride in uint2 entries
    __shared__ uint2 A2[2][BK][SA];
    __shared__ uint2 B2[2][BK][SA];

    int tid = threadIdx.x;
    int wid = tid >> 5, lane = tid & 31;
    int wm = (wid >> 2) * 64;    // warp row offset within block (0 or 64)
    int wn = (wid & 3) * 32;     // warp col offset within block
    int bm = blockIdx.y * 128;
    int bn = blockIdx.x * 128;

    // staging assignment: row = tid&127, k-half = tid>>7 (4 consecutive k)
    int lrow = tid & 127;
    int lcol = (tid >> 7) * 4;
    const float* Aptr = A + (size_t)(bm + lrow) * K + lcol;
    const float* Wptr = W + (size_t)(bn + lrow) * K + lcol;

    float acc[4][4][4];
    #pragma unroll
    for (int i = 0; i < 4; i++)
        #pragma unroll
        for (int j = 0; j < 4; j++)
            #pragma unroll
            for (int r = 0; r < 4; r++) acc[i][j][r] = 0.f;

    // prefetch first k-tile
    float4 av = *reinterpret_cast<const float4*>(Aptr);
    float4 wv = *reinterpret_cast<const float4*>(Wptr);

    int klane = lane & 3;        // k offset within fragment
    int glane = lane >> 2;       // group id

    int nIter = K / BK;
    for (int it = 0; it < nIter; it++) {
        int buf = it & 1;
        // split-convert + stage (hi,lo) interleaved
        {
            float va[4] = {av.x, av.y, av.z, av.w};
            float vw[4] = {wv.x, wv.y, wv.z, wv.w};
            #pragma unroll
            for (int j = 0; j < 4; j++) {
                int kk = lcol + j;
                uint32_t hi = cvt_tf32(va[j]);
                uint32_t lo = cvt_tf32(va[j] - __uint_as_float(hi));
                A2[buf][kk][lrow] = make_uint2(hi, lo);
                uint32_t whi = cvt_tf32(vw[j]);
                uint32_t wlo = cvt_tf32(vw[j] - __uint_as_float(whi));
                B2[buf][kk][lrow] = make_uint2(whi, wlo);
            }
        }
        __syncthreads();

        // prefetch next tile while computing this one
        if (it + 1 < nIter) {
            av = *reinterpret_cast<const float4*>(Aptr + (it + 1) * BK);
            wv = *reinterpret_cast<const float4*>(Wptr + (it + 1) * BK);
        }

        uint32_t ah[4][4], al[4][4], bh[4][2], bl[4][2];
        #pragma unroll
        for (int ti = 0; ti < 4; ti++) {
            int m = wm + ti * 16 + glane;
            uint2 p0 = A2[buf][klane][m];
            uint2 p1 = A2[buf][klane][m + 8];
            uint2 p2 = A2[buf][klane + 4][m];
            uint2 p3 = A2[buf][klane + 4][m + 8];
            ah[ti][0] = p0.x; al[ti][0] = p0.y;
            ah[ti][1] = p1.x; al[ti][1] = p1.y;
            ah[ti][2] = p2.x; al[ti][2] = p2.y;
            ah[ti][3] = p3.x; al[ti][3] = p3.y;
        }
        #pragma unroll
        for (int tj = 0; tj < 4; tj++) {
            int n = wn + tj * 8 + glane;
            uint2 q0 = B2[buf][klane][n];
            uint2 q1 = B2[buf][klane + 4][n];
            bh[tj][0] = q0.x; bl[tj][0] = q0.y;
            bh[tj][1] = q1.x; bl[tj][1] = q1.y;
        }
        #pragma unroll
        for (int ti = 0; ti < 4; ti++)
            #pragma unroll
            for (int tj = 0; tj < 4; tj++) {
                mma_tf32(acc[ti][tj], ah[ti], bh[tj]);
                mma_tf32(acc[ti][tj], al[ti], bh[tj]);
                mma_tf32(acc[ti][tj], ah[ti], bl[tj]);
            }
    }

    // epilogue: c0:(r0,c0) c1:(r0,c0+1) c2:(r0+8,c0) c3:(r0+8,c0+1)
    #pragma unroll
    for (int ti = 0; ti < 4; ti++) {
        int row0 = bm + wm + ti * 16 + glane;
        #pragma unroll
        for (int tj = 0; tj < 4; tj++) {
            int col = bn + wn + tj * 8 + 2 * klane;
            #pragma unroll
            for (int half = 0; half < 2; half++) {
                int row = row0 + half * 8;
                float v0 = acc[ti][tj][half * 2 + 0];
                float v1 = acc[ti][tj][half * 2 + 1];
                if (HAS_BIAS) { v0 += bias[col]; v1 += bias[col + 1]; }
                if (HAS_RES) {
                    float2 rv = *reinterpret_cast<const float2*>(res + (size_t)row * Nc + col);
                    v0 += rv.x; v1 += rv.y;
                }
                if (ACT == 1) { v0 = gelu_exact(v0); v1 = gelu_exact(v1); }
                else if (ACT == 2) { v0 = fmaxf(v0, 0.f); v1 = fmaxf(v1, 0.f); }
                else if (ACT == 3) {
                    v0 = 1.f / (1.f + expf(-v0));
                    v1 = 1.f / (1.f + expf(-v1));
                }
                if (OUT_TRANS) {
                    int n = row >> 2, b = row & 3;
                    C[((size_t)n * FF + col) * BB + b] = v0;
                    C[((size_t)n * FF + col + 1) * BB + b] = v1;
                } else {
                    float2 ov = make_float2(v0, v1);
                    *reinterpret_cast<float2*>(C + (size_t)row * Nc + col) = ov;
                }
            }
        }
    }
}

template <int ACT, bool HAS_BIAS, bool HAS_RES, bool OUT_TRANS>
static void launch_tc(const float* A, const float* W, const float* bias,
                      const float* res, float* C, int M, int Nc, int K) {
    dim3 grid(Nc / 128, M / 128);
    gemm_tc_kernel<ACT, HAS_BIAS, HAS_RES, OUT_TRANS><<<grid, 256>>>(A, W, bias, res, C, M, Nc, K);
}

// ---------------- fp32 fallback GEMM (small/odd shapes: SE1) ----------------
template <int ACT>
__global__ void __launch_bounds__(256)
gemm_kernel(const float* __restrict__ A, const float* __restrict__ W,
            float* __restrict__ C, int M, int Nc, int K)
{
    const int BM = 128, BN = 128, BK = 8, TM = 8, TN = 8;
    __shared__ float As[BK][BM];
    __shared__ float Bs[BK][BN];

    int bm = blockIdx.y * BM;
    int bn = blockIdx.x * BN;
    int tid = threadIdx.x;
    int tx = tid & 15;
    int ty = tid >> 4;

    int ld_row = tid >> 1;
    int ld_col = (tid & 1) * 4;

    int gr = bm + ld_row;
    int gw = bn + ld_row;
    bool a_ok = gr < M;
    bool w_ok = gw < Nc;
    const float* Aptr = A + (size_t)(a_ok ? gr : 0) * K + ld_col;
    const float* Wptr = W + (size_t)(w_ok ? gw : 0) * K + ld_col;

    float acc[TM][TN];
    #pragma unroll
    for (int i = 0; i < TM; i++)
        #pragma unroll
        for (int j = 0; j < TN; j++) acc[i][j] = 0.f;

    float4 av = a_ok ? *reinterpret_cast<const float4*>(Aptr)
                     : make_float4(0.f, 0.f, 0.f, 0.f);
    float4 wv = w_ok ? *reinterpret_cast<const float4*>(Wptr)
                     : make_float4(0.f, 0.f, 0.f, 0.f);

    for (int k0 = 0; k0 < K; k0 += BK) {
        As[ld_col + 0][ld_row] = av.x;
        As[ld_col + 1][ld_row] = av.y;
        As[ld_col + 2][ld_row] = av.z;
        As[ld_col + 3][ld_row] = av.w;
        Bs[ld_col + 0][ld_row] = wv.x;
        Bs[ld_col + 1][ld_row] = wv.y;
        Bs[ld_col + 2][ld_row] = wv.z;
        Bs[ld_col + 3][ld_row] = wv.w;
        __syncthreads();

        if (k0 + BK < K) {
            av = a_ok ? *reinterpret_cast<const float4*>(Aptr + k0 + BK)
                      : make_float4(0.f, 0.f, 0.f, 0.f);
            wv = w_ok ? *reinterpret_cast<const float4*>(Wptr + k0 + BK)
                      : make_float4(0.f, 0.f, 0.f, 0.f);
        }

        #pragma unroll
        for (int k = 0; k < BK; k++) {
            float4 a0 = *reinterpret_cast<const float4*>(&As[k][ty * TM]);
            float4 a1 = *reinterpret_cast<const float4*>(&As[k][ty * TM + 4]);
            float4 b0 = *reinterpret_cast<const float4*>(&Bs[k][tx * TN]);
            float4 b1 = *reinterpret_cast<const float4*>(&Bs[k][tx * TN + 4]);
            float ra[TM] = {a0.x, a0.y, a0.z, a0.w, a1.x, a1.y, a1.z, a1.w};
            float rb[TN] = {b0.x, b0.y, b0.z, b0.w, b1.x, b1.y, b1.z, b1.w};
            #pragma unroll
            for (int i = 0; i < TM; i++)
                #pragma unroll
                for (int j = 0; j < TN; j++)
                    acc[i][j] += ra[i] * rb[j];
        }
        __syncthreads();
    }

    #pragma unroll
    for (int i = 0; i < TM; i++) {
        int row = bm + ty * TM + i;
        if (row >= M) continue;
        #pragma unroll
        for (int j = 0; j < TN; j++) {
            int col = bn + tx * TN + j;
            if (col >= Nc) continue;
            float v = acc[i][j];
            if (ACT == 2) v = fmaxf(v, 0.f);
            C[(size_t)row * Nc + col] = v;
        }
    }
}

// ---------------- prep: branches -> token layout + gating context ----------------
__global__ void prep_kernel(const float* __restrict__ br,
                            float* __restrict__ T, float* __restrict__ ctx)
{
    int idx = blockIdx.x * blockDim.x + threadIdx.x;   // over N*F
    if (idx >= NN * FF) return;
    int n = idx >> 9, f = idx & 511;
    float4 v = *reinterpret_cast<const float4*>(br + (size_t)idx * 4);
    float mean = 0.25f * (v.x + v.y + v.z + v.w);
    float mx = fmaxf(fmaxf(v.x, v.y), fmaxf(v.z, v.w));
    ctx[(size_t)n * 1024 + f] = mean;
    ctx[(size_t)n * 1024 + 512 + f] = mx;
    size_t base = ((size_t)n * 4) * FF + f;
    T[base]        = v.x;
    T[base + 512]  = v.y;
    T[base + 1024] = v.z;
    T[base + 1536] = v.w;
}

// ---------------- row LayerNorm (512 features, 128 threads/row) ----------------
__global__ void ln_kernel(const float* __restrict__ X, const float* __restrict__ w,
                          const float* __restrict__ b, float* __restrict__ Y)
{
    __shared__ float shm[32];
    int r = blockIdx.x;
    int t = threadIdx.x;   // 128
    const float4* x = reinterpret_cast<const float4*>(X + (size_t)r * FF);
    float4 v = x[t];
    float s = v.x + v.y + v.z + v.w;
    float ss = v.x * v.x + v.y * v.y + v.z * v.z + v.w * v.w;
    block_reduce2(s, ss, shm);
    float mean = s * (1.f / 512.f);
    float var = ss * (1.f / 512.f) - mean * mean;
    float inv = rsqrtf(var + EPS);
    float4 wv = reinterpret_cast<const float4*>(w)[t];
    float4 bv = reinterpret_cast<const float4*>(b)[t];
    float4 o;
    o.x = (v.x - mean) * inv * wv.x + bv.x;
    o.y = (v.y - mean) * inv * wv.y + bv.y;
    o.z = (v.z - mean) * inv * wv.z + bv.z;
    o.w = (v.w - mean) * inv * wv.w + bv.w;
    reinterpret_cast<float4*>(Y + (size_t)r * FF)[t] = o;
}

// ---------------- attention (4 tokens, 4 heads, dh=128); warp per head ----------------
__global__ void attn_kernel(const float* __restrict__ qkv, float* __restrict__ ao)
{
    int n = blockIdx.x;
    int h = threadIdx.x >> 5;
    int lane = threadIdx.x & 31;
    const float scale = 0.08838834764831845f;   // 128^-0.5
    float q[4][4], k[4][4], v[4][4];
    const float* base = qkv + (size_t)n * 4 * 1536;
    #pragma unroll
    for (int i = 0; i < 4; i++) {
        const float* row = base + i * 1536 + h * 128;
        #pragma unroll
        for (int m = 0; m < 4; m++) {
            int d = lane + 32 * m;
            q[i][m] = row[d] * scale;
            k[i][m] = row[512 + d];
            v[i][m] = row[1024 + d];
        }
    }
    float att[4][4];
    #pragma unroll
    for (int i = 0; i < 4; i++)
        #pragma unroll
        for (int j = 0; j < 4; j++) {
            float p = q[i][0] * k[j][0] + q[i][1] * k[j][1]
                    + q[i][2] * k[j][2] + q[i][3] * k[j][3];
            #pragma unroll
            for (int o = 16; o; o >>= 1) p += __shfl_xor_sync(0xffffffffu, p, o);
            att[i][j] = p;
        }
    #pragma unroll
    for (int i = 0; i < 4; i++) {
        float mx = fmaxf(fmaxf(att[i][0], att[i][1]), fmaxf(att[i][2], att[i][3]));
        float e0 = expf(att[i][0] - mx), e1 = expf(att[i][1] - mx);
        float e2 = expf(att[i][2] - mx), e3 = expf(att[i][3] - mx);
        float inv = 1.f / (e0 + e1 + e2 + e3);
        att[i][0] = e0 * inv; att[i][1] = e1 * inv;
        att[i][2] = e2 * inv; att[i][3] = e3 * inv;
    }
    #pragma unroll
    for (int i = 0; i < 4; i++)
        #pragma unroll
        for (int m = 0; m < 4; m++) {
            float o = att[i][0] * v[0][m] + att[i][1] * v[1][m]
                    + att[i][2] * v[2][m] + att[i][3] * v[3][m];
            ao[((size_t)(n * 4 + i)) * FF + h * 128 + lane + 32 * m] = o;
        }
}

// ---------------- depthwise conv (k=3 over B) + SE squeeze ----------------
__global__ void dw_kernel(float* __restrict__ x1, const float* __restrict__ dw,
                          float* __restrict__ s)
{
    int idx = blockIdx.x * blockDim.x + threadIdx.x;   // over N*F
    if (idx >= NN * FF) return;
    int n = idx >> 9, f = idx & 511;
    size_t base = ((size_t)n * 4) * FF + f;
    float a = x1[base], b = x1[base + 512], c = x1[base + 1024], d = x1[base + 1536];
    float w0 = dw[f * 3], w1 = dw[f * 3 + 1], w2 = dw[f * 3 + 2];
    float y0 = w1 * a + w2 * b;
    float y1 = w0 * a + w1 * b + w2 * c;
    float y2 = w0 * b + w1 * c + w2 * d;
    float y3 = w0 * c + w1 * d;
    x1[base] = y0; x1[base + 512] = y1; x1[base + 1024] = y2; x1[base + 1536] = y3;
    s[idx] = 0.25f * (y0 + y1 + y2 + y3);
}

// ---------------- SE scale + GroupNorm(1 group over F*B) + GELU ----------------
__global__ void gn_kernel(float* __restrict__ x1, const float* __restrict__ s2,
                          const float* __restrict__ gnw, const float* __restrict__ gnb)
{
    __shared__ float shm[32];
    int n = blockIdx.x;
    int t = threadIdx.x;   // 256
    float vals[8];
    float s = 0.f, ss = 0.f;
    #pragma unroll
    for (int j = 0; j < 8; j++) {
        int e = t + 256 * j;
        int b = e >> 9, f = e & 511;
        float v = x1[((size_t)(n * 4 + b)) * FF + f] * s2[(size_t)n * FF + f];
        vals[j] = v; s += v; ss += v * v;
    }
    block_reduce2(s, ss, shm);
    float mean = s * (1.f / 2048.f);
    float var = ss * (1.f / 2048.f) - mean * mean;
    float inv = rsqrtf(var + EPS);
    #pragma unroll
    for (int j = 0; j < 8; j++) {
        int e = t + 256 * j;
        int b = e >> 9, f = e & 511;
        float y = (vals[j] - mean) * inv * gnw[f] + gnb[f];
        x1[((size_t)(n * 4 + b)) * FF + f] = gelu_exact(y);
    }
}

// ---------------- gate second layer + softmax -> alpha ----------------
__global__ void gate2_kernel(const float* __restrict__ gh, const float* __restrict__ w2,
                             const float* __restrict__ b2, float* __restrict__ alpha)
{
    int warp = threadIdx.x >> 5, lane = threadIdx.x & 31;
    int n = blockIdx.x * 8 + warp;
    if (n >= NN) return;
    float gv[4];
    #pragma unroll
    for (int m = 0; m < 4; m++) gv[m] = gh[(size_t)n * GH + lane + 32 * m];
    float lg[3];
    #pragma unroll
    for (int e = 0; e < 3; e++) {
        float p = 0.f;
        #pragma unroll
        for (int m = 0; m < 4; m++) p += gv[m] * w2[e * GH + lane + 32 * m];
        #pragma unroll
        for (int o = 16; o; o >>= 1) p += __shfl_xor_sync(0xffffffffu, p, o);
        lg[e] = p + b2[e];
    }
    if (lane == 0) {
        float mx = fmaxf(lg[0], fmaxf(lg[1], lg[2]));
        float e0 = expf(lg[0] - mx), e1 = expf(lg[1] - mx), e2 = expf(lg[2] - mx);
        float inv = 1.f / (e0 + e1 + e2);
        alpha[n * 3 + 0] = e0 * inv;
        alpha[n * 3 + 1] = e1 * inv;
        alpha[n * 3 + 2] = e2 * inv;
    }
}

// ---------------- fuse experts with alpha (in place into x1) ----------------
__global__ void fuse_kernel(float* __restrict__ x1, const float* __restrict__ x2,
                            const float* __restrict__ x3, const float* __restrict__ alpha)
{
    int idx = blockIdx.x * blockDim.x + threadIdx.x;   // over M*128 float4
    if (idx >= MM * (FF / 4)) return;
    int r = idx >> 7;
    int n = r >> 2;
    float a0 = alpha[n * 3 + 0], a1 = alpha[n * 3 + 1], a2 = alpha[n * 3 + 2];
    float4 u = reinterpret_cast<float4*>(x1)[idx];
    float4 v = reinterpret_cast<const float4*>(x2)[idx];
    float4 w = reinterpret_cast<const float4*>(x3)[idx];
    u.x = a0 * u.x + a1 * v.x + a2 * w.x;
    u.y = a0 * u.y + a1 * v.y + a2 * w.y;
    u.z = a0 * u.z + a1 * v.z + a2 * w.z;
    u.w = a0 * u.w + a1 * v.w + a2 * w.w;
    reinterpret_cast<float4*>(x1)[idx] = u;
}

// ---------------- host launch ----------------
static float* sym(const void* symbol) {
    void* p = nullptr;
    cudaGetSymbolAddress(&p, symbol);
    return reinterpret_cast<float*>(p);
}

extern "C" void kernel_launch(void* const* d_in, const int* in_sizes, int n_in,
                              void* d_out, int out_size)
{
    const float* branches   = (const float*)d_in[0];
    const float* conv_pw_w  = (const float*)d_in[1];
    const float* conv_dw_w  = (const float*)d_in[2];
    const float* gn_w       = (const float*)d_in[3];
    const float* gn_b       = (const float*)d_in[4];
    const float* se_w1      = (const float*)d_in[5];
    const float* se_w2      = (const float*)d_in[6];
    const float* ln_attn_w  = (const float*)d_in[7];
    const float* ln_attn_b  = (const float*)d_in[8];
    const float* in_proj_w  = (const float*)d_in[9];
    const float* in_proj_b  = (const float*)d_in[10];
    const float* attn_out_w = (const float*)d_in[11];
    const float* attn_out_b = (const float*)d_in[12];
    const float* ln_ffn_w   = (const float*)d_in[13];
    const float* ln_ffn_b   = (const float*)d_in[14];
    const float* ffn_w1     = (const float*)d_in[15];
    const float* ffn_b1     = (const float*)d_in[16];
    const float* ffn_w2     = (const float*)d_in[17];
    const float* ffn_b2     = (const float*)d_in[18];
    const float* mlp_ln_w   = (const float*)d_in[19];
    const float* mlp_ln_b   = (const float*)d_in[20];
    const float* mlp_w1     = (const float*)d_in[21];
    const float* mlp_b1     = (const float*)d_in[22];
    const float* mlp_w2     = (const float*)d_in[23];
    const float* mlp_b2     = (const float*)d_in[24];
    const float* gate_w1    = (const float*)d_in[25];
    const float* gate_b1    = (const float*)d_in[26];
    const float* gate_w2    = (const float*)d_in[27];
    const float* gate_b2    = (const float*)d_in[28];
    const float* outp_w     = (const float*)d_in[29];
    float* out = (float*)d_out;

    float* T   = sym(g_T);
    float* scr = sym(g_scr);
    float* qkv = sym(g_qkv);
    float* t2  = sym(g_t2);
    float* x1  = sym(g_x1);
    float* x3  = sym(g_x3);
    float* ctx = sym(g_ctx);
    float* s   = sym(g_s);
    float* s1  = sym(g_s1);
    float* s2  = sym(g_s2);
    float* gh  = sym(g_gh);
    float* alpha = sym(g_alpha);

    const int EW_BLOCKS = (NN * FF) / 256;   // 32768

    // 0. tokens + gating context
    prep_kernel<<<EW_BLOCKS, 256>>>(branches, T, ctx);

    // gating
    launch_tc<1, true, false, false>(ctx, gate_w1, gate_b1, nullptr, gh, NN, GH, 1024);
    gate2_kernel<<<NN / 8, 256>>>(gh, gate_w2, gate_b2, alpha);

    // ---- conv expert ----
    launch_tc<0, false, false, false>(T, conv_pw_w, nullptr, nullptr, x1, MM, FF, FF);
    dw_kernel<<<EW_BLOCKS, 256>>>(x1, conv_dw_w, s);
    {   // SE1: Nc=64 -> fp32 fallback
        dim3 grid((SE_DIM + 127) / 128, (NN + 127) / 128);
        gemm_kernel<2><<<grid, 256>>>(s, se_w1, s1, NN, SE_DIM, FF);
    }
    launch_tc<3, false, false, false>(s1, se_w2, nullptr, nullptr, s2, NN, FF, SE_DIM);
    gn_kernel<<<NN, 256>>>(x1, s2, gn_w, gn_b);

    // ---- attention expert ----
    ln_kernel<<<MM, 128>>>(T, ln_attn_w, ln_attn_b, scr);
    launch_tc<0, true, false, false>(scr, in_proj_w, in_proj_b, nullptr, qkv, MM, 1536, FF);
    attn_kernel<<<NN, 128>>>(qkv, scr);
    launch_tc<0, true, true, false>(scr, attn_out_w, attn_out_b, T, t2, MM, FF, FF);
    ln_kernel<<<MM, 128>>>(t2, ln_ffn_w, ln_ffn_b, scr);
    launch_tc<1, true, false, false>(scr, ffn_w1, ffn_b1, nullptr, qkv, MM, 1024, FF);
    launch_tc<0, true, true, false>(qkv, ffn_w2, ffn_b2, t2, t2, MM, FF, 1024);
    // t2 now holds x2

    // ---- MLP expert ----
    ln_kernel<<<MM, 128>>>(T, mlp_ln_w, mlp_ln_b, scr);
    launch_tc<1, true, false, false>(scr, mlp_w1, mlp_b1, nullptr, qkv, MM, 1024, FF);
    launch_tc<0, true, true, false>(qkv, mlp_w2, mlp_b2, T, x3, MM, FF, 1024);

    // ---- fuse + output projection (transposed store to (n,o,b)) ----
    fuse_kernel<<<(MM * (FF / 4)) / 256, 256>>>(x1, t2, x3, alpha);
    launch_tc<0, false, false, true>(x1, outp_w, nullptr, nullptr, out, MM, FF, FF);
}